// round 2
// baseline (speedup 1.0000x reference)
#include <cuda_runtime.h>
#include <math.h>

#define B_  2
#define L_  2048
#define D_  1024
#define H_  16
#define E_  64
#define W_  256
#define NT  (B_*L_)   // 4096 tokens
#define N3  (3*D_)    // 3072

// Scratch (no allocations allowed): qkv [NT, 3072], attention out [NT, 1024]
__device__ float g_qkv[NT * N3];
__device__ float g_att[NT * D_];

// ---------------------------------------------------------------------------
// C[M,N] = A[M,K] @ W[N,K]^T + bias[N]   (both operands K-major, "NT" GEMM)
// 128x128 block tile, BK=16, 256 threads, 8x8 per thread.
// ---------------------------------------------------------------------------
__global__ __launch_bounds__(256) void gemm_nt_bias(
    const float* __restrict__ A, const float* __restrict__ Wt,
    const float* __restrict__ bias, float* __restrict__ C,
    int M, int N, int K)
{
    __shared__ float As[16][132];   // [k][m]
    __shared__ float Bs[16][132];   // [k][n]

    const int tid = threadIdx.x;
    const int tx  = tid & 15;       // n-dir
    const int ty  = tid >> 4;       // m-dir
    const int n0  = blockIdx.x * 128;
    const int m0  = blockIdx.y * 128;

    float acc[8][8];
    #pragma unroll
    for (int i = 0; i < 8; i++)
        #pragma unroll
        for (int j = 0; j < 8; j++) acc[i][j] = 0.f;

    for (int k0 = 0; k0 < K; k0 += 16) {
        // Load 128x16 tiles of A and W, store K-transposed into smem.
        #pragma unroll
        for (int t = 0; t < 2; t++) {
            int idx = tid + t * 256;          // 0..511
            int row = idx >> 2;               // 0..127
            int k4  = (idx & 3) << 2;         // 0,4,8,12
            float4 a = *(const float4*)&A [(size_t)(m0 + row) * K + k0 + k4];
            As[k4+0][row] = a.x; As[k4+1][row] = a.y;
            As[k4+2][row] = a.z; As[k4+3][row] = a.w;
            float4 w = *(const float4*)&Wt[(size_t)(n0 + row) * K + k0 + k4];
            Bs[k4+0][row] = w.x; Bs[k4+1][row] = w.y;
            Bs[k4+2][row] = w.z; Bs[k4+3][row] = w.w;
        }
        __syncthreads();

        #pragma unroll
        for (int k = 0; k < 16; k++) {
            float ra[8], rb[8];
            #pragma unroll
            for (int i = 0; i < 8; i++) ra[i] = As[k][ty*8 + i];
            #pragma unroll
            for (int j = 0; j < 8; j++) rb[j] = Bs[k][tx*8 + j];
            #pragma unroll
            for (int i = 0; i < 8; i++)
                #pragma unroll
                for (int j = 0; j < 8; j++) acc[i][j] += ra[i] * rb[j];
        }
        __syncthreads();
    }

    #pragma unroll
    for (int i = 0; i < 8; i++) {
        int m = m0 + ty*8 + i;
        #pragma unroll
        for (int j = 0; j < 8; j += 4) {
            int n = n0 + tx*8 + j;
            float4 o;
            o.x = acc[i][j+0] + bias[n+0];
            o.y = acc[i][j+1] + bias[n+1];
            o.z = acc[i][j+2] + bias[n+2];
            o.w = acc[i][j+3] + bias[n+3];
            *(float4*)&C[(size_t)m * N + n] = o;
        }
    }
}

// ---------------------------------------------------------------------------
// Sliding-window causal attention. One block = (b, h, 64-query tile).
// Online softmax over 64-key chunks in [max(0, q0-256), q0].
// Thread map: warp w owns query rows w*8..w*8+7; lane owns 2 key-cols /
// 2 head-dim cols. smem: Q[64][64], K^T/P (reused) [64][64], V[64][64] = 48KB.
// ---------------------------------------------------------------------------
__global__ __launch_bounds__(256) void attn_kernel(
    const float* __restrict__ qkv, float* __restrict__ att)
{
    __shared__ float Qs [64][64];   // [i][e]
    __shared__ float KPs[64][64];   // K^T: [e][j]; later reused as P: [i][j]
    __shared__ float Vs [64][64];   // [j][e]

    const int q0   = blockIdx.x * 64;
    const int h    = blockIdx.y;
    const int b    = blockIdx.z;
    const int tid  = threadIdx.x;
    const int lane = tid & 31;
    const int wid  = tid >> 5;
    const int hoff = h * E_;

    // Load Q tile (row = token, 64 contiguous floats per row)
    for (int idx = tid; idx < 64 * 16; idx += 256) {
        int row = idx >> 4;
        int c4  = (idx & 15) << 2;
        float4 v = *(const float4*)&qkv[(size_t)(b*L_ + q0 + row) * N3 + hoff + c4];
        *(float4*)&Qs[row][c4] = v;
    }

    float m_run[8], l_run[8], o0[8], o1[8];
    #pragma unroll
    for (int r = 0; r < 8; r++) { m_run[r] = -1e30f; l_run[r] = 0.f; o0[r] = 0.f; o1[r] = 0.f; }

    const int cbeg = (q0 >= W_) ? (q0 - W_) : 0;
    const float scale = 0.125f;   // 1/sqrt(64)

    // Q-load must be visible before first S compute
    __syncthreads();

    for (int c = cbeg; c <= q0; c += 64) {
        // Load K chunk (transposed) and V chunk
        for (int idx = tid; idx < 64 * 16; idx += 256) {
            int row = idx >> 4;                 // key j within chunk
            int c4  = (idx & 15) << 2;          // e
            size_t base = (size_t)(b*L_ + c + row) * N3 + hoff;
            float4 kv = *(const float4*)&qkv[base + D_   + c4];
            KPs[c4+0][row] = kv.x; KPs[c4+1][row] = kv.y;
            KPs[c4+2][row] = kv.z; KPs[c4+3][row] = kv.w;
            float4 vv = *(const float4*)&qkv[base + 2*D_ + c4];
            *(float4*)&Vs[row][c4] = vv;
        }
        __syncthreads();

        // S = Q K^T for this thread's 8 rows x 2 cols
        float s0[8], s1[8];
        #pragma unroll
        for (int r = 0; r < 8; r++) { s0[r] = 0.f; s1[r] = 0.f; }
        #pragma unroll
        for (int e = 0; e < 64; e += 2) {
            float2 ka = *(float2*)&KPs[e    ][lane*2];
            float2 kb = *(float2*)&KPs[e + 1][lane*2];
            #pragma unroll
            for (int r = 0; r < 8; r++) {
                float2 qq = *(float2*)&Qs[wid*8 + r][e];
                s0[r] += qq.x*ka.x + qq.y*kb.x;
                s1[r] += qq.x*ka.y + qq.y*kb.y;
            }
        }
        __syncthreads();   // all warps done reading KPs as K^T

        // mask + online softmax + write P into KPs
        #pragma unroll
        for (int r = 0; r < 8; r++) {
            int i  = q0 + wid*8 + r;
            int j0 = c + lane*2;
            int j1 = j0 + 1;
            bool v0 = (j0 <= i) && (i - j0 < W_);
            bool v1 = (j1 <= i) && (i - j1 < W_);
            float a0 = v0 ? s0[r]*scale : -1e30f;
            float a1 = v1 ? s1[r]*scale : -1e30f;
            float mx = fmaxf(a0, a1);
            #pragma unroll
            for (int off = 16; off > 0; off >>= 1)
                mx = fmaxf(mx, __shfl_xor_sync(0xffffffffu, mx, off));
            float mn = fmaxf(m_run[r], mx);
            float p0 = v0 ? __expf(a0 - mn) : 0.f;
            float p1 = v1 ? __expf(a1 - mn) : 0.f;
            float rs = p0 + p1;
            #pragma unroll
            for (int off = 16; off > 0; off >>= 1)
                rs += __shfl_xor_sync(0xffffffffu, rs, off);
            float f = __expf(m_run[r] - mn);   // 0 when m_run == -1e30 and mn finite
            l_run[r] = l_run[r]*f + rs;
            m_run[r] = mn;
            o0[r] *= f; o1[r] *= f;
            KPs[wid*8 + r][lane*2    ] = p0;
            KPs[wid*8 + r][lane*2 + 1] = p1;
        }
        __syncwarp();   // P rows are produced & consumed by the same warp

        // O += P @ V  (this warp's 8 rows, this lane's 2 e-cols)
        #pragma unroll 8
        for (int j = 0; j < 64; j++) {
            float2 vv = *(float2*)&Vs[j][lane*2];
            #pragma unroll
            for (int r = 0; r < 8; r++) {
                float pp = KPs[wid*8 + r][j];
                o0[r] += pp * vv.x;
                o1[r] += pp * vv.y;
            }
        }
        __syncthreads();   // done with Vs/KPs before next chunk overwrites
    }

    // normalize and store: att[b, l, h*64 + e]
    #pragma unroll
    for (int r = 0; r < 8; r++) {
        int i = q0 + wid*8 + r;
        float inv = 1.0f / l_run[r];
        float2 o; o.x = o0[r]*inv; o.y = o1[r]*inv;
        *(float2*)&att[(size_t)(b*L_ + i) * D_ + hoff + lane*2] = o;
    }
}

// ---------------------------------------------------------------------------
extern "C" void kernel_launch(void* const* d_in, const int* in_sizes, int n_in,
                              void* d_out, int out_size)
{
    const float* x      = (const float*)d_in[0];
    const float* w_qkv  = (const float*)d_in[1];
    const float* b_qkv  = (const float*)d_in[2];
    const float* w_proj = (const float*)d_in[3];
    const float* b_proj = (const float*)d_in[4];
    float* out = (float*)d_out;

    float *qkv_p = nullptr, *att_p = nullptr;
    cudaGetSymbolAddress((void**)&qkv_p, g_qkv);   // lookup only, capture-safe
    cudaGetSymbolAddress((void**)&att_p, g_att);

    // 1) qkv = x @ w_qkv^T + b_qkv          [4096, 3072]
    dim3 g1(N3 / 128, NT / 128);
    gemm_nt_bias<<<g1, 256>>>(x, w_qkv, b_qkv, qkv_p, NT, N3, D_);

    // 2) sliding-window attention            [4096, 1024]
    dim3 ga(L_ / 64, H_, B_);
    attn_kernel<<<ga, 256>>>(qkv_p, att_p);

    // 3) out = att @ w_proj^T + b_proj       [4096, 1024]
    dim3 g3(D_ / 128, NT / 128);
    gemm_nt_bias<<<g3, 256>>>(att_p, w_proj, b_proj, out, NT, D_, D_);
}

// round 5
// speedup vs baseline: 1.7413x; 1.7413x over previous
#include <cuda_runtime.h>
#include <cuda_bf16.h>
#include <stdint.h>
#include <math.h>

#define B_  2
#define L_  2048
#define D_  1024
#define H_  16
#define E_  64
#define W_  256
#define NT  (B_*L_)   // 4096 tokens
#define N3  (3*D_)    // 3072

// Scratch (no allocations allowed)
__device__ float g_qkv[NT * N3];
__device__ float g_att[NT * D_];

// ===========================================================================
// Helpers
// ===========================================================================
__device__ __forceinline__ uint32_t smem_u32(const void* p) {
    uint32_t a;
    asm("{ .reg .u64 t; cvta.to.shared.u64 t, %1; cvt.u32.u64 %0, t; }"
        : "=r"(a) : "l"(p));
    return a;
}
__device__ __forceinline__ uint32_t pack_bf16x2(__nv_bfloat16 a, __nv_bfloat16 b) {
    __nv_bfloat162 t = __halves2bfloat162(a, b);
    return *(uint32_t*)&t;
}
__device__ __forceinline__ void ldsm_x4(uint32_t* r, uint32_t addr) {
    asm volatile("ldmatrix.sync.aligned.m8n8.x4.shared.b16 {%0,%1,%2,%3}, [%4];"
                 : "=r"(r[0]), "=r"(r[1]), "=r"(r[2]), "=r"(r[3]) : "r"(addr));
}
__device__ __forceinline__ void mma16816(float* d, const uint32_t* a, const uint32_t* b) {
    asm volatile(
        "mma.sync.aligned.m16n8k16.row.col.f32.bf16.bf16.f32 "
        "{%0,%1,%2,%3}, {%4,%5,%6,%7}, {%8,%9}, {%0,%1,%2,%3};"
        : "+f"(d[0]), "+f"(d[1]), "+f"(d[2]), "+f"(d[3])
        : "r"(a[0]), "r"(a[1]), "r"(a[2]), "r"(a[3]), "r"(b[0]), "r"(b[1]));
}

// fp32x4 -> bf16 hi/lo split, stored as two uint2 (4 bf16 each)
__device__ __forceinline__ void split_store(char* hi, char* lo, uint32_t off, float4 v) {
    __nv_bfloat16 h0 = __float2bfloat16_rn(v.x);
    __nv_bfloat16 h1 = __float2bfloat16_rn(v.y);
    __nv_bfloat16 h2 = __float2bfloat16_rn(v.z);
    __nv_bfloat16 h3 = __float2bfloat16_rn(v.w);
    uint2 hv = { pack_bf16x2(h0, h1), pack_bf16x2(h2, h3) };
    uint2 lv = { pack_bf16x2(__float2bfloat16_rn(v.x - __bfloat162float(h0)),
                             __float2bfloat16_rn(v.y - __bfloat162float(h1))),
                 pack_bf16x2(__float2bfloat16_rn(v.z - __bfloat162float(h2)),
                             __float2bfloat16_rn(v.w - __bfloat162float(h3))) };
    *(uint2*)(hi + off) = hv;
    *(uint2*)(lo + off) = lv;
}

// ===========================================================================
// Split-bf16 HMMA GEMM:  C[M,N] = A[M,K] @ W[N,K]^T + bias[N]  (fp32 I/O)
// A*W ~= Ah*Wh + Ah*Wl + Al*Wh.  CTA 128x128, BK=32, 256 thr, warp tile 64x32.
// smem: 4 bf16 tiles (Ah,Al,Wh,Wl) 128x32, row pitch 80B, double-buffered.
// ===========================================================================
#define PITCH   80
#define TILE_B  (128 * PITCH)     // 10240
#define STAGE_B (4 * TILE_B)      // 40960
#define SMEM_DYN (2 * STAGE_B)    // 81920

__global__ __launch_bounds__(256) void gemm_tc(
    const float* __restrict__ A, const float* __restrict__ Wt,
    const float* __restrict__ bias, float* __restrict__ C,
    int M, int N, int K)
{
    extern __shared__ char sm[];

    const int tid  = threadIdx.x;
    const int lane = tid & 31;
    const int wid  = tid >> 5;
    const int wm   = wid >> 2;        // 0..1  -> m offset wm*64
    const int wn   = wid & 3;         // 0..3  -> n offset wn*32
    const int n0   = blockIdx.x * 128;
    const int m0   = blockIdx.y * 128;

    float acc[4][4][4];
    #pragma unroll
    for (int i = 0; i < 4; i++)
        #pragma unroll
        for (int j = 0; j < 4; j++)
            #pragma unroll
            for (int r = 0; r < 4; r++) acc[i][j][r] = 0.f;

    // --- gmem prefetch registers: 4 float4 for A, 4 for W per thread ---
    float4 pa[4], pw[4];

    const int KT = K / 32;

    // prologue: load k-block 0
    #pragma unroll
    for (int t = 0; t < 4; t++) {
        int idx = tid + t * 256;          // 0..1023
        int row = idx >> 3;               // 0..127
        int f4  = idx & 7;                // 0..7
        pa[t] = *(const float4*)&A [(size_t)(m0 + row) * K + f4 * 4];
        pw[t] = *(const float4*)&Wt[(size_t)(n0 + row) * K + f4 * 4];
    }
    {
        char* stg = sm;
        #pragma unroll
        for (int t = 0; t < 4; t++) {
            int idx = tid + t * 256;
            int row = idx >> 3;
            int f4  = idx & 7;
            uint32_t off = row * PITCH + f4 * 8;
            split_store(stg,              stg + TILE_B,     off, pa[t]);
            split_store(stg + 2 * TILE_B, stg + 3 * TILE_B, off, pw[t]);
        }
    }
    __syncthreads();

    for (int it = 0; it < KT; it++) {
        const int s = it & 1;
        char* cur = sm + s * STAGE_B;

        // prefetch next k-block into registers
        if (it + 1 < KT) {
            int k0 = (it + 1) * 32;
            #pragma unroll
            for (int t = 0; t < 4; t++) {
                int idx = tid + t * 256;
                int row = idx >> 3;
                int f4  = idx & 7;
                pa[t] = *(const float4*)&A [(size_t)(m0 + row) * K + k0 + f4 * 4];
                pw[t] = *(const float4*)&Wt[(size_t)(n0 + row) * K + k0 + f4 * 4];
            }
        }

        // ---- compute from cur ----
        const uint32_t bAh = smem_u32(cur);
        const uint32_t bAl = bAh + TILE_B;
        const uint32_t bWh = bAh + 2 * TILE_B;
        const uint32_t bWl = bAh + 3 * TILE_B;

        #pragma unroll
        for (int ks = 0; ks < 2; ks++) {
            uint32_t ah[4][4], al[4][4], bh[4][2], bl[4][2];

            // A fragments: lane l -> row (l&15), col-block (l>>4)*16B, +ks*32B
            const uint32_t aoff0 = (uint32_t)(wm * 64 + (lane & 15)) * PITCH
                                 + (uint32_t)((lane >> 4) * 16 + ks * 32);
            #pragma unroll
            for (int mi = 0; mi < 4; mi++) {
                uint32_t off = aoff0 + (uint32_t)(mi * 16 * PITCH);
                ldsm_x4(ah[mi], bAh + off);
                ldsm_x4(al[mi], bAl + off);
            }

            // B fragments: mat = lane>>3; row = wn*32 + (mat>>1)*8 + (lane&7);
            // col = (mat&1)*16B + ks*32B
            const int mat = lane >> 3;
            const uint32_t boff0 = (uint32_t)(wn * 32 + ((mat >> 1) << 3) + (lane & 7)) * PITCH
                                 + (uint32_t)(((mat & 1) << 4) + ks * 32);
            #pragma unroll
            for (int nb = 0; nb < 2; nb++) {
                uint32_t t4[4];
                uint32_t off = boff0 + (uint32_t)(nb * 16 * PITCH);
                ldsm_x4(t4, bWh + off);
                bh[nb*2][0] = t4[0]; bh[nb*2][1] = t4[1];
                bh[nb*2+1][0] = t4[2]; bh[nb*2+1][1] = t4[3];
                ldsm_x4(t4, bWl + off);
                bl[nb*2][0] = t4[0]; bl[nb*2][1] = t4[1];
                bl[nb*2+1][0] = t4[2]; bl[nb*2+1][1] = t4[3];
            }

            #pragma unroll
            for (int mi = 0; mi < 4; mi++)
                #pragma unroll
                for (int nj = 0; nj < 4; nj++) {
                    mma16816(acc[mi][nj], ah[mi], bh[nj]);
                    mma16816(acc[mi][nj], ah[mi], bl[nj]);
                    mma16816(acc[mi][nj], al[mi], bh[nj]);
                }
        }
        __syncthreads();     // everyone done reading cur

        if (it + 1 < KT) {
            char* nxt = sm + (s ^ 1) * STAGE_B;
            #pragma unroll
            for (int t = 0; t < 4; t++) {
                int idx = tid + t * 256;
                int row = idx >> 3;
                int f4  = idx & 7;
                uint32_t off = row * PITCH + f4 * 8;
                split_store(nxt,              nxt + TILE_B,     off, pa[t]);
                split_store(nxt + 2 * TILE_B, nxt + 3 * TILE_B, off, pw[t]);
            }
            __syncthreads();
        }
    }

    // ---- epilogue: acc + bias -> C ----
    #pragma unroll
    for (int mi = 0; mi < 4; mi++) {
        int r0 = m0 + wm * 64 + mi * 16 + (lane >> 2);
        #pragma unroll
        for (int nj = 0; nj < 4; nj++) {
            int col = n0 + wn * 32 + nj * 8 + (lane & 3) * 2;
            float2 bb = *(const float2*)&bias[col];
            float2 v0 = { acc[mi][nj][0] + bb.x, acc[mi][nj][1] + bb.y };
            float2 v1 = { acc[mi][nj][2] + bb.x, acc[mi][nj][3] + bb.y };
            *(float2*)&C[(size_t)r0 * N + col]       = v0;
            *(float2*)&C[(size_t)(r0 + 8) * N + col] = v1;
        }
    }
}

// ---------------------------------------------------------------------------
// Sliding-window causal attention (unchanged, proven correct).
// ---------------------------------------------------------------------------
__global__ __launch_bounds__(256) void attn_kernel(
    const float* __restrict__ qkv, float* __restrict__ att)
{
    __shared__ float Qs [64][64];
    __shared__ float KPs[64][64];
    __shared__ float Vs [64][64];

    const int q0   = blockIdx.x * 64;
    const int h    = blockIdx.y;
    const int b    = blockIdx.z;
    const int tid  = threadIdx.x;
    const int lane = tid & 31;
    const int wid  = tid >> 5;
    const int hoff = h * E_;

    for (int idx = tid; idx < 64 * 16; idx += 256) {
        int row = idx >> 4;
        int c4  = (idx & 15) << 2;
        float4 v = *(const float4*)&qkv[(size_t)(b*L_ + q0 + row) * N3 + hoff + c4];
        *(float4*)&Qs[row][c4] = v;
    }

    float m_run[8], l_run[8], o0[8], o1[8];
    #pragma unroll
    for (int r = 0; r < 8; r++) { m_run[r] = -1e30f; l_run[r] = 0.f; o0[r] = 0.f; o1[r] = 0.f; }

    const int cbeg = (q0 >= W_) ? (q0 - W_) : 0;
    const float scale = 0.125f;

    __syncthreads();

    for (int c = cbeg; c <= q0; c += 64) {
        for (int idx = tid; idx < 64 * 16; idx += 256) {
            int row = idx >> 4;
            int c4  = (idx & 15) << 2;
            size_t base = (size_t)(b*L_ + c + row) * N3 + hoff;
            float4 kv = *(const float4*)&qkv[base + D_   + c4];
            KPs[c4+0][row] = kv.x; KPs[c4+1][row] = kv.y;
            KPs[c4+2][row] = kv.z; KPs[c4+3][row] = kv.w;
            float4 vv = *(const float4*)&qkv[base + 2*D_ + c4];
            *(float4*)&Vs[row][c4] = vv;
        }
        __syncthreads();

        float s0[8], s1[8];
        #pragma unroll
        for (int r = 0; r < 8; r++) { s0[r] = 0.f; s1[r] = 0.f; }
        #pragma unroll
        for (int e = 0; e < 64; e += 2) {
            float2 ka = *(float2*)&KPs[e    ][lane*2];
            float2 kb = *(float2*)&KPs[e + 1][lane*2];
            #pragma unroll
            for (int r = 0; r < 8; r++) {
                float2 qq = *(float2*)&Qs[wid*8 + r][e];
                s0[r] += qq.x*ka.x + qq.y*kb.x;
                s1[r] += qq.x*ka.y + qq.y*kb.y;
            }
        }
        __syncthreads();

        #pragma unroll
        for (int r = 0; r < 8; r++) {
            int i  = q0 + wid*8 + r;
            int j0 = c + lane*2;
            int j1 = j0 + 1;
            bool v0 = (j0 <= i) && (i - j0 < W_);
            bool v1 = (j1 <= i) && (i - j1 < W_);
            float a0 = v0 ? s0[r]*scale : -1e30f;
            float a1 = v1 ? s1[r]*scale : -1e30f;
            float mx = fmaxf(a0, a1);
            #pragma unroll
            for (int off = 16; off > 0; off >>= 1)
                mx = fmaxf(mx, __shfl_xor_sync(0xffffffffu, mx, off));
            float mn = fmaxf(m_run[r], mx);
            float p0 = v0 ? __expf(a0 - mn) : 0.f;
            float p1 = v1 ? __expf(a1 - mn) : 0.f;
            float rs = p0 + p1;
            #pragma unroll
            for (int off = 16; off > 0; off >>= 1)
                rs += __shfl_xor_sync(0xffffffffu, rs, off);
            float f = __expf(m_run[r] - mn);
            l_run[r] = l_run[r]*f + rs;
            m_run[r] = mn;
            o0[r] *= f; o1[r] *= f;
            KPs[wid*8 + r][lane*2    ] = p0;
            KPs[wid*8 + r][lane*2 + 1] = p1;
        }
        __syncwarp();

        #pragma unroll 8
        for (int j = 0; j < 64; j++) {
            float2 vv = *(float2*)&Vs[j][lane*2];
            #pragma unroll
            for (int r = 0; r < 8; r++) {
                float pp = KPs[wid*8 + r][j];
                o0[r] += pp * vv.x;
                o1[r] += pp * vv.y;
            }
        }
        __syncthreads();
    }

    #pragma unroll
    for (int r = 0; r < 8; r++) {
        int i = q0 + wid*8 + r;
        float inv = 1.0f / l_run[r];
        float2 o; o.x = o0[r]*inv; o.y = o1[r]*inv;
        *(float2*)&att[(size_t)(b*L_ + i) * D_ + hoff + lane*2] = o;
    }
}

// ---------------------------------------------------------------------------
extern "C" void kernel_launch(void* const* d_in, const int* in_sizes, int n_in,
                              void* d_out, int out_size)
{
    const float* x      = (const float*)d_in[0];
    const float* w_qkv  = (const float*)d_in[1];
    const float* b_qkv  = (const float*)d_in[2];
    const float* w_proj = (const float*)d_in[3];
    const float* b_proj = (const float*)d_in[4];
    float* out = (float*)d_out;

    float *qkv_p = nullptr, *att_p = nullptr;
    cudaGetSymbolAddress((void**)&qkv_p, g_qkv);
    cudaGetSymbolAddress((void**)&att_p, g_att);

    cudaFuncSetAttribute(gemm_tc, cudaFuncAttributeMaxDynamicSharedMemorySize, SMEM_DYN);

    // 1) qkv = x @ w_qkv^T + b_qkv          [4096, 3072]
    gemm_tc<<<dim3(N3 / 128, NT / 128), 256, SMEM_DYN>>>(x, w_qkv, b_qkv, qkv_p, NT, N3, D_);

    // 2) sliding-window attention            [4096, 1024]
    attn_kernel<<<dim3(L_ / 64, H_, B_), 256>>>(qkv_p, att_p);

    // 3) out = att @ w_proj^T + b_proj       [4096, 1024]
    gemm_tc<<<dim3(D_ / 128, NT / 128), 256, SMEM_DYN>>>(att_p, w_proj, b_proj, out, NT, D_, D_);
}

// round 6
// speedup vs baseline: 2.0046x; 1.1512x over previous
#include <cuda_runtime.h>
#include <cuda_bf16.h>
#include <stdint.h>
#include <math.h>

#define B_  2
#define L_  2048
#define D_  1024
#define H_  16
#define E_  64
#define W_  256
#define NT  (B_*L_)   // 4096 tokens
#define N3  (3*D_)    // 3072

// Scratch (no allocations allowed)
__device__ float g_qkv[NT * N3];
__device__ __nv_bfloat16 g_xh [NT * D_],  g_xl [NT * D_];
__device__ __nv_bfloat16 g_wqh[N3 * D_],  g_wql[N3 * D_];
__device__ __nv_bfloat16 g_wph[D_ * D_],  g_wpl[D_ * D_];
__device__ __nv_bfloat16 g_ath[NT * D_],  g_atl[NT * D_];

// ===========================================================================
// Helpers
// ===========================================================================
__device__ __forceinline__ uint32_t smem_u32(const void* p) {
    uint32_t a;
    asm("{ .reg .u64 t; cvta.to.shared.u64 t, %1; cvt.u32.u64 %0, t; }"
        : "=r"(a) : "l"(p));
    return a;
}
__device__ __forceinline__ uint32_t pack_bf16x2(__nv_bfloat16 a, __nv_bfloat16 b) {
    __nv_bfloat162 t = __halves2bfloat162(a, b);
    return *(uint32_t*)&t;
}
__device__ __forceinline__ void ldsm_x4(uint32_t* r, uint32_t addr) {
    asm volatile("ldmatrix.sync.aligned.m8n8.x4.shared.b16 {%0,%1,%2,%3}, [%4];"
                 : "=r"(r[0]), "=r"(r[1]), "=r"(r[2]), "=r"(r[3]) : "r"(addr));
}
__device__ __forceinline__ void mma16816(float* d, const uint32_t* a, const uint32_t* b) {
    asm volatile(
        "mma.sync.aligned.m16n8k16.row.col.f32.bf16.bf16.f32 "
        "{%0,%1,%2,%3}, {%4,%5,%6,%7}, {%8,%9}, {%0,%1,%2,%3};"
        : "+f"(d[0]), "+f"(d[1]), "+f"(d[2]), "+f"(d[3])
        : "r"(a[0]), "r"(a[1]), "r"(a[2]), "r"(a[3]), "r"(b[0]), "r"(b[1]));
}
#define CP_ASYNC16(dst, src) \
    asm volatile("cp.async.cg.shared.global [%0], [%1], 16;" :: "r"(dst), "l"(src))
#define CP_COMMIT() asm volatile("cp.async.commit_group;" ::: "memory")
#define CP_WAIT(n)  asm volatile("cp.async.wait_group %0;" :: "n"(n) : "memory")

// fp32x4 -> hi/lo bf16x4 (as uint2 pairs)
__device__ __forceinline__ void split4(float4 v, uint2* hv, uint2* lv) {
    __nv_bfloat16 h0 = __float2bfloat16_rn(v.x);
    __nv_bfloat16 h1 = __float2bfloat16_rn(v.y);
    __nv_bfloat16 h2 = __float2bfloat16_rn(v.z);
    __nv_bfloat16 h3 = __float2bfloat16_rn(v.w);
    hv->x = pack_bf16x2(h0, h1); hv->y = pack_bf16x2(h2, h3);
    lv->x = pack_bf16x2(__float2bfloat16_rn(v.x - __bfloat162float(h0)),
                        __float2bfloat16_rn(v.y - __bfloat162float(h1)));
    lv->y = pack_bf16x2(__float2bfloat16_rn(v.z - __bfloat162float(h2)),
                        __float2bfloat16_rn(v.w - __bfloat162float(h3)));
}

// ===========================================================================
// Elementwise fp32 -> bf16 hi/lo split (one-time pre-pass)
// ===========================================================================
__global__ __launch_bounds__(256) void split_kernel(
    const float* __restrict__ src, __nv_bfloat16* __restrict__ hi,
    __nv_bfloat16* __restrict__ lo, int n4)
{
    int i = blockIdx.x * 256 + threadIdx.x;
    if (i >= n4) return;
    float4 v = *(const float4*)&src[i * 4];
    uint2 hv, lv;
    split4(v, &hv, &lv);
    *(uint2*)&hi[i * 4] = hv;
    *(uint2*)&lo[i * 4] = lv;
}

// ===========================================================================
// Split-bf16 HMMA GEMM, pre-split operands, cp.async 2-stage pipeline.
// C[M,N] = (Ah+Al)[M,K] @ (Wh+Wl)[N,K]^T + bias  ~  AhWh + AhWl + AlWh
// CTA 128x128, BK=32, 256 thr, warp tile 64x32. smem pitch 80B.
// ===========================================================================
#define PITCH    80
#define TILE_B   (128 * PITCH)     // 10240
#define STAGE_B  (4 * TILE_B)      // 40960
#define SMEM_DYN (2 * STAGE_B)     // 81920

__global__ __launch_bounds__(256) void gemm_tc(
    const __nv_bfloat16* __restrict__ Ah, const __nv_bfloat16* __restrict__ Al,
    const __nv_bfloat16* __restrict__ Wh, const __nv_bfloat16* __restrict__ Wl,
    const float* __restrict__ bias, float* __restrict__ C,
    int M, int N, int K)
{
    extern __shared__ char sm[];

    const int tid  = threadIdx.x;
    const int lane = tid & 31;
    const int wid  = tid >> 5;
    const int wm   = wid >> 2;        // 0..1  -> m offset wm*64
    const int wn   = wid & 3;         // 0..3  -> n offset wn*32
    const int n0   = blockIdx.x * 128;
    const int m0   = blockIdx.y * 128;

    // cp.async source row/chunk for this thread (2 rows per tile)
    const int rowA0 = tid >> 2;              // 0..63
    const int chA   = tid & 3;               // 16B chunk id
    // tile issue: rows rowA0 and rowA0+64

    float acc[4][4][4];
    #pragma unroll
    for (int i = 0; i < 4; i++)
        #pragma unroll
        for (int j = 0; j < 4; j++)
            #pragma unroll
            for (int r = 0; r < 4; r++) acc[i][j][r] = 0.f;

    const int KT = K / 32;

    // issue one stage's loads (4 tiles x 128 rows x 4 chunks of 16B)
    auto issue = [&](int s, int k0) {
        char* stg = sm + s * STAGE_B;
        uint32_t base = smem_u32(stg);
        #pragma unroll
        for (int t = 0; t < 2; t++) {
            int row  = rowA0 + t * 64;
            uint32_t doff = (uint32_t)(row * PITCH + chA * 16);
            const __nv_bfloat16* sa = Ah + (size_t)(m0 + row) * K + k0 + chA * 8;
            const __nv_bfloat16* sl = Al + (size_t)(m0 + row) * K + k0 + chA * 8;
            const __nv_bfloat16* wh = Wh + (size_t)(n0 + row) * K + k0 + chA * 8;
            const __nv_bfloat16* wl = Wl + (size_t)(n0 + row) * K + k0 + chA * 8;
            CP_ASYNC16(base + doff,              sa);
            CP_ASYNC16(base + TILE_B + doff,     sl);
            CP_ASYNC16(base + 2 * TILE_B + doff, wh);
            CP_ASYNC16(base + 3 * TILE_B + doff, wl);
        }
        CP_COMMIT();
    };

    issue(0, 0);

    for (int it = 0; it < KT; it++) {
        const int s = it & 1;

        if (it + 1 < KT) { issue(s ^ 1, (it + 1) * 32); CP_WAIT(1); }
        else             { CP_WAIT(0); }
        __syncthreads();

        const uint32_t bAh = smem_u32(sm + s * STAGE_B);
        const uint32_t bAl = bAh + TILE_B;
        const uint32_t bWh = bAh + 2 * TILE_B;
        const uint32_t bWl = bAh + 3 * TILE_B;

        #pragma unroll
        for (int ks = 0; ks < 2; ks++) {
            uint32_t ah[4][4], al[4][4], bh[4][2], bl[4][2];

            const uint32_t aoff0 = (uint32_t)(wm * 64 + (lane & 15)) * PITCH
                                 + (uint32_t)((lane >> 4) * 16 + ks * 32);
            #pragma unroll
            for (int mi = 0; mi < 4; mi++) {
                uint32_t off = aoff0 + (uint32_t)(mi * 16 * PITCH);
                ldsm_x4(ah[mi], bAh + off);
                ldsm_x4(al[mi], bAl + off);
            }

            const int mat = lane >> 3;
            const uint32_t boff0 = (uint32_t)(wn * 32 + ((mat >> 1) << 3) + (lane & 7)) * PITCH
                                 + (uint32_t)(((mat & 1) << 4) + ks * 32);
            #pragma unroll
            for (int nb = 0; nb < 2; nb++) {
                uint32_t t4[4];
                uint32_t off = boff0 + (uint32_t)(nb * 16 * PITCH);
                ldsm_x4(t4, bWh + off);
                bh[nb*2][0] = t4[0]; bh[nb*2][1] = t4[1];
                bh[nb*2+1][0] = t4[2]; bh[nb*2+1][1] = t4[3];
                ldsm_x4(t4, bWl + off);
                bl[nb*2][0] = t4[0]; bl[nb*2][1] = t4[1];
                bl[nb*2+1][0] = t4[2]; bl[nb*2+1][1] = t4[3];
            }

            #pragma unroll
            for (int mi = 0; mi < 4; mi++)
                #pragma unroll
                for (int nj = 0; nj < 4; nj++) {
                    mma16816(acc[mi][nj], ah[mi], bh[nj]);
                    mma16816(acc[mi][nj], ah[mi], bl[nj]);
                    mma16816(acc[mi][nj], al[mi], bh[nj]);
                }
        }
        __syncthreads();   // all reads of this stage done before it is re-filled
    }

    // ---- epilogue: acc + bias -> C ----
    #pragma unroll
    for (int mi = 0; mi < 4; mi++) {
        int r0 = m0 + wm * 64 + mi * 16 + (lane >> 2);
        #pragma unroll
        for (int nj = 0; nj < 4; nj++) {
            int col = n0 + wn * 32 + nj * 8 + (lane & 3) * 2;
            float2 bb = *(const float2*)&bias[col];
            float2 v0 = { acc[mi][nj][0] + bb.x, acc[mi][nj][1] + bb.y };
            float2 v1 = { acc[mi][nj][2] + bb.x, acc[mi][nj][3] + bb.y };
            *(float2*)&C[(size_t)r0 * N + col]       = v0;
            *(float2*)&C[(size_t)(r0 + 8) * N + col] = v1;
        }
    }
}

// ---------------------------------------------------------------------------
// Sliding-window causal attention. Epilogue now writes bf16 hi/lo directly.
// ---------------------------------------------------------------------------
__global__ __launch_bounds__(256) void attn_kernel(
    const float* __restrict__ qkv,
    __nv_bfloat16* __restrict__ ath, __nv_bfloat16* __restrict__ atl)
{
    __shared__ float Qs [64][64];
    __shared__ float KPs[64][64];
    __shared__ float Vs [64][64];

    const int q0   = blockIdx.x * 64;
    const int h    = blockIdx.y;
    const int b    = blockIdx.z;
    const int tid  = threadIdx.x;
    const int lane = tid & 31;
    const int wid  = tid >> 5;
    const int hoff = h * E_;

    for (int idx = tid; idx < 64 * 16; idx += 256) {
        int row = idx >> 4;
        int c4  = (idx & 15) << 2;
        float4 v = *(const float4*)&qkv[(size_t)(b*L_ + q0 + row) * N3 + hoff + c4];
        *(float4*)&Qs[row][c4] = v;
    }

    float m_run[8], l_run[8], o0[8], o1[8];
    #pragma unroll
    for (int r = 0; r < 8; r++) { m_run[r] = -1e30f; l_run[r] = 0.f; o0[r] = 0.f; o1[r] = 0.f; }

    const int cbeg = (q0 >= W_) ? (q0 - W_) : 0;
    const float scale = 0.125f;

    __syncthreads();

    for (int c = cbeg; c <= q0; c += 64) {
        for (int idx = tid; idx < 64 * 16; idx += 256) {
            int row = idx >> 4;
            int c4  = (idx & 15) << 2;
            size_t base = (size_t)(b*L_ + c + row) * N3 + hoff;
            float4 kv = *(const float4*)&qkv[base + D_   + c4];
            KPs[c4+0][row] = kv.x; KPs[c4+1][row] = kv.y;
            KPs[c4+2][row] = kv.z; KPs[c4+3][row] = kv.w;
            float4 vv = *(const float4*)&qkv[base + 2*D_ + c4];
            *(float4*)&Vs[row][c4] = vv;
        }
        __syncthreads();

        float s0[8], s1[8];
        #pragma unroll
        for (int r = 0; r < 8; r++) { s0[r] = 0.f; s1[r] = 0.f; }
        #pragma unroll
        for (int e = 0; e < 64; e += 2) {
            float2 ka = *(float2*)&KPs[e    ][lane*2];
            float2 kb = *(float2*)&KPs[e + 1][lane*2];
            #pragma unroll
            for (int r = 0; r < 8; r++) {
                float2 qq = *(float2*)&Qs[wid*8 + r][e];
                s0[r] += qq.x*ka.x + qq.y*kb.x;
                s1[r] += qq.x*ka.y + qq.y*kb.y;
            }
        }
        __syncthreads();

        #pragma unroll
        for (int r = 0; r < 8; r++) {
            int i  = q0 + wid*8 + r;
            int j0 = c + lane*2;
            int j1 = j0 + 1;
            bool v0 = (j0 <= i) && (i - j0 < W_);
            bool v1 = (j1 <= i) && (i - j1 < W_);
            float a0 = v0 ? s0[r]*scale : -1e30f;
            float a1 = v1 ? s1[r]*scale : -1e30f;
            float mx = fmaxf(a0, a1);
            #pragma unroll
            for (int off = 16; off > 0; off >>= 1)
                mx = fmaxf(mx, __shfl_xor_sync(0xffffffffu, mx, off));
            float mn = fmaxf(m_run[r], mx);
            float p0 = v0 ? __expf(a0 - mn) : 0.f;
            float p1 = v1 ? __expf(a1 - mn) : 0.f;
            float rs = p0 + p1;
            #pragma unroll
            for (int off = 16; off > 0; off >>= 1)
                rs += __shfl_xor_sync(0xffffffffu, rs, off);
            float f = __expf(m_run[r] - mn);
            l_run[r] = l_run[r]*f + rs;
            m_run[r] = mn;
            o0[r] *= f; o1[r] *= f;
            KPs[wid*8 + r][lane*2    ] = p0;
            KPs[wid*8 + r][lane*2 + 1] = p1;
        }
        __syncwarp();

        #pragma unroll 8
        for (int j = 0; j < 64; j++) {
            float2 vv = *(float2*)&Vs[j][lane*2];
            #pragma unroll
            for (int r = 0; r < 8; r++) {
                float pp = KPs[wid*8 + r][j];
                o0[r] += pp * vv.x;
                o1[r] += pp * vv.y;
            }
        }
        __syncthreads();
    }

    #pragma unroll
    for (int r = 0; r < 8; r++) {
        int i = q0 + wid*8 + r;
        float inv = 1.0f / l_run[r];
        float vx = o0[r]*inv, vy = o1[r]*inv;
        __nv_bfloat16 hx = __float2bfloat16_rn(vx);
        __nv_bfloat16 hy = __float2bfloat16_rn(vy);
        size_t off = (size_t)(b*L_ + i) * D_ + hoff + lane*2;
        *(uint32_t*)&ath[off] = pack_bf16x2(hx, hy);
        *(uint32_t*)&atl[off] = pack_bf16x2(
            __float2bfloat16_rn(vx - __bfloat162float(hx)),
            __float2bfloat16_rn(vy - __bfloat162float(hy)));
    }
}

// ---------------------------------------------------------------------------
extern "C" void kernel_launch(void* const* d_in, const int* in_sizes, int n_in,
                              void* d_out, int out_size)
{
    const float* x      = (const float*)d_in[0];
    const float* w_qkv  = (const float*)d_in[1];
    const float* b_qkv  = (const float*)d_in[2];
    const float* w_proj = (const float*)d_in[3];
    const float* b_proj = (const float*)d_in[4];
    float* out = (float*)d_out;

    float* qkv_p = nullptr;
    __nv_bfloat16 *xh, *xl, *wqh, *wql, *wph, *wpl, *ath, *atl;
    cudaGetSymbolAddress((void**)&qkv_p, g_qkv);
    cudaGetSymbolAddress((void**)&xh,  g_xh);  cudaGetSymbolAddress((void**)&xl,  g_xl);
    cudaGetSymbolAddress((void**)&wqh, g_wqh); cudaGetSymbolAddress((void**)&wql, g_wql);
    cudaGetSymbolAddress((void**)&wph, g_wph); cudaGetSymbolAddress((void**)&wpl, g_wpl);
    cudaGetSymbolAddress((void**)&ath, g_ath); cudaGetSymbolAddress((void**)&atl, g_atl);

    cudaFuncSetAttribute(gemm_tc, cudaFuncAttributeMaxDynamicSharedMemorySize, SMEM_DYN);

    // 0) one-time fp32 -> bf16 hi/lo splits
    split_kernel<<<(NT*D_/4 + 255)/256, 256>>>(x,      xh,  xl,  NT*D_/4);
    split_kernel<<<(N3*D_/4 + 255)/256, 256>>>(w_qkv,  wqh, wql, N3*D_/4);
    split_kernel<<<(D_*D_/4 + 255)/256, 256>>>(w_proj, wph, wpl, D_*D_/4);

    // 1) qkv = x @ w_qkv^T + b_qkv          [4096, 3072]
    gemm_tc<<<dim3(N3 / 128, NT / 128), 256, SMEM_DYN>>>(xh, xl, wqh, wql, b_qkv, qkv_p, NT, N3, D_);

    // 2) sliding-window attention -> bf16 hi/lo   [4096, 1024]
    attn_kernel<<<dim3(L_ / 64, H_, B_), 256>>>(qkv_p, ath, atl);

    // 3) out = att @ w_proj^T + b_proj       [4096, 1024]
    gemm_tc<<<dim3(D_ / 128, NT / 128), 256, SMEM_DYN>>>(ath, atl, wph, wpl, b_proj, out, NT, D_, D_);
}